// round 1
// baseline (speedup 1.0000x reference)
#include <cuda_runtime.h>

#define BSZ 64
#define SEQ 2048
#define DM 12
#define DI 24
#define DS 16
#define DTR 4
#define DC 4
#define NCHUNK 32
#define CLEN (SEQ / NCHUNK)   /* 64 */
#define TILE 128
#define STEPS 16
#define NLANES (DI * DS)      /* 384 */

// Scratch (static device arrays — no allocation in kernel_launch).
// g_seq layout per (b,t): 64 floats = [dt0,w0, dt1,w1, ... dt23,w23, B0..B15]
// where w_d = dt_d * xc_d.
__device__ float g_seq[(size_t)BSZ * SEQ * 64];
__device__ float g_Ap[BSZ * NCHUNK * NLANES];
__device__ float g_Bp[BSZ * NCHUNK * NLANES];

__device__ __forceinline__ float siluf(float v) {
    return v / (1.0f + __expf(-v));
}
__device__ __forceinline__ float softplusf(float v) {
    // stable: max(v,0) + log1p(exp(-|v|))  (matches jax.nn.softplus)
    return fmaxf(v, 0.0f) + log1pf(__expf(-fabsf(v)));
}

// ---------------------------------------------------------------------------
// Kernel 1: front-end. One thread per timestep (block = one batch x 128 t's).
// in_proj -> causal depthwise conv -> silu -> x_proj -> dt (softplus).
// Writes dt, dt*xc, B to g_seq.
// ---------------------------------------------------------------------------
__global__ __launch_bounds__(TILE) void k_frontend(
    const float* __restrict__ x, const float* __restrict__ ipw,
    const float* __restrict__ cw, const float* __restrict__ cb,
    const float* __restrict__ xpw, const float* __restrict__ dpw,
    const float* __restrict__ dpb)
{
    __shared__ float s_xin[TILE + 3][DI + 1];   // +1 pad: avoid stride-24 bank conflicts
    __shared__ float s_ipw[DI][DM];
    __shared__ float s_cw[DI][DC];
    __shared__ float s_cb[DI];
    __shared__ float s_xpw[DTR + DS][DI];
    __shared__ float s_dpw[DI][DTR];
    __shared__ float s_dpb[DI];

    const int tid = threadIdx.x;
    for (int i = tid; i < DI * DM; i += TILE) s_ipw[i / DM][i % DM] = ipw[i];
    for (int i = tid; i < DI * DC; i += TILE) s_cw[i / DC][i % DC] = cw[i];
    for (int i = tid; i < DI; i += TILE) { s_cb[i] = cb[i]; s_dpb[i] = dpb[i]; }
    for (int i = tid; i < (DTR + DS) * DI; i += TILE) s_xpw[i / DI][i % DI] = xpw[i];
    for (int i = tid; i < DI * DTR; i += TILE) s_dpw[i / DTR][i % DTR] = dpw[i];
    __syncthreads();

    const int b  = blockIdx.y;
    const int t0 = blockIdx.x * TILE;
    const int tt = t0 + tid;

    // x_in for my own timestep
    {
        const float* xr = x + ((size_t)(b * SEQ) + tt) * DM;
        float xv[DM];
        #pragma unroll
        for (int k = 0; k < DM; k++) xv[k] = xr[k];
        #pragma unroll
        for (int d = 0; d < DI; d++) {
            float a = 0.0f;
            #pragma unroll
            for (int k = 0; k < DM; k++) a = fmaf(xv[k], s_ipw[d][k], a);
            s_xin[tid + 3][d] = a;
        }
    }
    // halo: t0-3 .. t0-1 (zeros for t<0)
    if (tid < 3) {
        const int th = t0 - 3 + tid;
        if (th >= 0) {
            const float* xr = x + ((size_t)(b * SEQ) + th) * DM;
            float xv[DM];
            #pragma unroll
            for (int k = 0; k < DM; k++) xv[k] = xr[k];
            #pragma unroll
            for (int d = 0; d < DI; d++) {
                float a = 0.0f;
                #pragma unroll
                for (int k = 0; k < DM; k++) a = fmaf(xv[k], s_ipw[d][k], a);
                s_xin[tid][d] = a;
            }
        } else {
            #pragma unroll
            for (int d = 0; d < DI; d++) s_xin[tid][d] = 0.0f;
        }
    }
    __syncthreads();

    // causal depthwise conv + silu
    float xc[DI];
    #pragma unroll
    for (int d = 0; d < DI; d++) {
        float a = s_cb[d];
        #pragma unroll
        for (int j = 0; j < DC; j++) a = fmaf(s_xin[tid + j][d], s_cw[d][j], a);
        xc[d] = siluf(a);
    }

    // x_proj: dt_low (4) and B (16). (C only needed at t=L-1, done in k_final.)
    float dtl[DTR], Bm[DS];
    #pragma unroll
    for (int e = 0; e < DTR; e++) {
        float a = 0.0f;
        #pragma unroll
        for (int d = 0; d < DI; d++) a = fmaf(xc[d], s_xpw[e][d], a);
        dtl[e] = a;
    }
    #pragma unroll
    for (int e = 0; e < DS; e++) {
        float a = 0.0f;
        #pragma unroll
        for (int d = 0; d < DI; d++) a = fmaf(xc[d], s_xpw[DTR + e][d], a);
        Bm[e] = a;
    }

    float* o = g_seq + ((size_t)(b * SEQ) + tt) * 64;
    #pragma unroll
    for (int d = 0; d < DI; d++) {
        float v = s_dpb[d];
        #pragma unroll
        for (int r = 0; r < DTR; r++) v = fmaf(dtl[r], s_dpw[d][r], v);
        const float dt = softplusf(v);
        float2 p = make_float2(dt, dt * xc[d]);
        *(float2*)&o[2 * d] = p;
    }
    #pragma unroll
    for (int e = 0; e < DS; e += 4) {
        float4 p = make_float4(Bm[e], Bm[e + 1], Bm[e + 2], Bm[e + 3]);
        *(float4*)&o[48 + e] = p;
    }
}

// ---------------------------------------------------------------------------
// Kernel 2: chunked scan. Block = (b, chunk), 384 threads = (d, s) lanes.
// Within the chunk: h = exp(dt*A)*h + (dt*xc)*B, starting from h=0.
// Chunk transfer coefficient: A_c = exp(A * sum(dt)) (== prod of dA).
// ---------------------------------------------------------------------------
__global__ __launch_bounds__(NLANES) void k_scan(const float* __restrict__ A_log)
{
    __shared__ float sm[STEPS * 64];
    const int tid = threadIdx.x;
    const int d = tid >> 4;
    const int s = tid & 15;
    const int b = blockIdx.y;
    const int c = blockIdx.x;

    const float A = -__expf(A_log[d * DS + s]);
    const float* base = g_seq + ((size_t)(b * SEQ) + (size_t)c * CLEN) * 64;

    float h = 0.0f, sdt = 0.0f;
    #pragma unroll 1
    for (int st = 0; st < CLEN / STEPS; st++) {
        __syncthreads();
        #pragma unroll
        for (int i = tid; i < STEPS * 64; i += NLANES)
            sm[i] = base[st * STEPS * 64 + i];
        __syncthreads();
        #pragma unroll
        for (int k = 0; k < STEPS; k++) {
            const float2 dw = *(const float2*)&sm[k * 64 + 2 * d];   // dt, dt*xc
            const float  Bv = sm[k * 64 + 48 + s];
            const float  dA = __expf(dw.x * A);
            h = fmaf(dA, h, dw.y * Bv);
            sdt += dw.x;
        }
    }
    const int idx = (b * NCHUNK + c) * NLANES + tid;
    g_Ap[idx] = __expf(A * sdt);
    g_Bp[idx] = h;
}

// ---------------------------------------------------------------------------
// Kernel 3: combine chunks + last-timestep epilogue. One block per batch.
// ---------------------------------------------------------------------------
__global__ __launch_bounds__(NLANES) void k_final(
    const float* __restrict__ x, const float* __restrict__ ipw,
    const float* __restrict__ cw, const float* __restrict__ cb,
    const float* __restrict__ xpw, const float* __restrict__ Dp,
    const float* __restrict__ opw, const float* __restrict__ fcw,
    const float* __restrict__ fcb, float* __restrict__ out)
{
    const int tid = threadIdx.x;
    const int b = blockIdx.x;
    const int d = tid >> 4;
    const int s = tid & 15;

    // sequential chunk combine (32 iterations, coalesced loads)
    float h = 0.0f;
    const float* ap = g_Ap + (size_t)b * NCHUNK * NLANES + tid;
    const float* bp = g_Bp + (size_t)b * NCHUNK * NLANES + tid;
    #pragma unroll
    for (int c = 0; c < NCHUNK; c++)
        h = fmaf(ap[c * NLANES], h, bp[c * NLANES]);

    __shared__ float s_xin4[DC][DI];
    __shared__ float s_xc[DI], s_zsilu[DI], s_C[DS], s_y[DI], s_o[DM];

    // x_in at the last 4 timesteps (for conv at t=L-1)
    if (tid < DC * DI) {
        const int j = tid / DI, dd = tid % DI;
        const float* xr = x + ((size_t)(b * SEQ) + (SEQ - DC + j)) * DM;
        float a = 0.0f;
        #pragma unroll
        for (int k = 0; k < DM; k++) a = fmaf(xr[k], ipw[dd * DM + k], a);
        s_xin4[j][dd] = a;
    }
    // silu(z) at t=L-1 (in_proj rows 24..47)
    if (tid >= 128 && tid < 128 + DI) {
        const int dd = tid - 128;
        const float* xr = x + ((size_t)(b * SEQ) + (SEQ - 1)) * DM;
        float a = 0.0f;
        #pragma unroll
        for (int k = 0; k < DM; k++) a = fmaf(xr[k], ipw[(DI + dd) * DM + k], a);
        s_zsilu[dd] = siluf(a);
    }
    __syncthreads();

    if (tid < DI) {
        float a = cb[tid];
        #pragma unroll
        for (int j = 0; j < DC; j++) a = fmaf(s_xin4[j][tid], cw[tid * DC + j], a);
        s_xc[tid] = siluf(a);
    }
    __syncthreads();

    // C at t=L-1 (x_proj rows 20..35)
    if (tid < DS) {
        float a = 0.0f;
        #pragma unroll
        for (int dd = 0; dd < DI; dd++)
            a = fmaf(s_xc[dd], xpw[(DTR + DS + tid) * DI + dd], a);
        s_C[tid] = a;
    }
    __syncthreads();

    // y[d] = sum_s h[d,s]*C[s]  (16-lane shuffle reduction; offsets < 16 stay in-group)
    float part = h * s_C[s];
    part += __shfl_xor_sync(0xffffffffu, part, 8);
    part += __shfl_xor_sync(0xffffffffu, part, 4);
    part += __shfl_xor_sync(0xffffffffu, part, 2);
    part += __shfl_xor_sync(0xffffffffu, part, 1);
    if (s == 0) {
        float y = part + s_xc[d] * Dp[d];
        s_y[d] = y * s_zsilu[d];
    }
    __syncthreads();

    if (tid < DM) {
        float a = 0.0f;
        #pragma unroll
        for (int dd = 0; dd < DI; dd++) a = fmaf(s_y[dd], opw[tid * DI + dd], a);
        s_o[tid] = a * fcw[tid];
    }
    __syncthreads();

    if (tid == 0) {
        float a = fcb[0];
        #pragma unroll
        for (int e = 0; e < DM; e++) a += s_o[e];
        out[b] = a;
    }
}

// ---------------------------------------------------------------------------
extern "C" void kernel_launch(void* const* d_in, const int* in_sizes, int n_in,
                              void* d_out, int out_size)
{
    const float* x     = (const float*)d_in[0];
    const float* ipw   = (const float*)d_in[1];
    const float* cw    = (const float*)d_in[2];
    const float* cb    = (const float*)d_in[3];
    const float* xpw   = (const float*)d_in[4];
    const float* dpw   = (const float*)d_in[5];
    const float* dpb   = (const float*)d_in[6];
    const float* A_log = (const float*)d_in[7];
    const float* Dp    = (const float*)d_in[8];
    const float* opw   = (const float*)d_in[9];
    const float* fcw   = (const float*)d_in[10];
    const float* fcb   = (const float*)d_in[11];
    float* out = (float*)d_out;

    dim3 gA(SEQ / TILE, BSZ);
    k_frontend<<<gA, TILE>>>(x, ipw, cw, cb, xpw, dpw, dpb);

    dim3 gB(NCHUNK, BSZ);
    k_scan<<<gB, NLANES>>>(A_log);

    k_final<<<BSZ, NLANES>>>(x, ipw, cw, cb, xpw, Dp, opw, fcw, fcb, out);
}